// round 15
// baseline (speedup 1.0000x reference)
#include <cuda_runtime.h>
#include <cstdint>

// Problem constants
#define BATCH 4
#define NPTS  200000
#define NGRID 128            // NX = NY = NZ = 128
#define NVOX  (BATCH * NGRID * NGRID * NGRID)   // 8,388,608 voxels
#define NWORDS (NVOX / 32)                      // 262,144 uint32 per tensor
#define PTS_PER_THREAD 4

// Scratch: 2 tensors x 1 MB bitmask (static device array, no alloc).
// Zeroed by the LEADING zero_kernel every invocation (no cross-call state).
// Expand NEVER writes the mask (R4/R6/R10: in-expand clears are toxic to the
// streaming-store bandwidth at every write granularity tried).
__device__ unsigned int g_mask[2][NWORDS];

// ---------------------------------------------------------------------------
// Kernel 1 (leading): zero both bitmasks. First node of every replay pays a
// ~4 us fixed tax (measured constant across R3/R8/R9/R14) — let the cheap
// 2 MB clear absorb it.
// ---------------------------------------------------------------------------
__global__ void zero_kernel() {
    const unsigned idx = blockIdx.x * blockDim.x + threadIdx.x;  // < 131072
    ((uint4*)g_mask)[idx] = make_uint4(0u, 0u, 0u, 0u);
}

// ---------------------------------------------------------------------------
// Kernel 2: scatter points into occupancy bitmasks (RED.OR, L2-resident).
// At its measured floor (~7-8 us = spread-REDG wavefront throughput; R12/R13
// proved issue rate and load MLP are not binding). 4 points per thread via
// 3 x LDG.128. Reciprocals once per block via smem — bit-identical to
// per-thread __fdiv_rn (rel_err == 0.0 verified since R3).
//
// Numeric model: XLA arcp form  q = (p - 0.5*v) * (1/v), 1/v correctly
// rounded. rintf = round-half-even = jnp.round.
// ---------------------------------------------------------------------------
__device__ __forceinline__ int voxel_coord(float p, float v, float rinv) {
    float half    = __fmul_rn(v, 0.5f);        // exact
    float shifted = __fsub_rn(p, half);        // IEEE sub
    float q       = __fmul_rn(shifted, rinv);  // multiply by CR reciprocal
    return (int)rintf(q) + 64;
}

__global__ void scatter_kernel(const float* __restrict__ pts_a,
                               const float* __restrict__ pts_b,
                               const float* __restrict__ vs) {
    const int b = blockIdx.y;                  // batch
    const int t = blockIdx.z;                  // tensor (0=a, 1=b)

    __shared__ float s_v[3], s_r[3];
    if (threadIdx.x < 3u) {
        const float v = vs[b * 3 + threadIdx.x];
        s_v[threadIdx.x] = v;
        s_r[threadIdx.x] = __fdiv_rn(1.0f, v); // CR reciprocal, once per block
    }
    __syncthreads();

    const unsigned tid = blockIdx.x * blockDim.x + threadIdx.x;
    const unsigned p0  = tid * PTS_PER_THREAD;           // first point
    if (p0 >= NPTS) return;                              // NPTS % 4 == 0

    const float* __restrict__ pts =
        ((t == 0) ? pts_a : pts_b) + (size_t)b * (NPTS * 3);

    // 4 points = 12 floats = 3 x float4 (16 B aligned)
    const float4* __restrict__ q4 = (const float4*)(pts + (size_t)p0 * 3);
    const float4 A = q4[0];
    const float4 B = q4[1];
    const float4 C = q4[2];

    const float xs[4] = {A.x, A.w, B.z, C.y};
    const float ys[4] = {A.y, B.x, B.w, C.z};
    const float zs[4] = {A.z, B.y, C.x, C.w};

    const float v0 = s_v[0], v1 = s_v[1], v2 = s_v[2];
    const float r0 = s_r[0], r1 = s_r[1], r2 = s_r[2];

#pragma unroll
    for (int u = 0; u < 4; u++) {
        const int i = voxel_coord(xs[u], v0, r0);
        const int j = voxel_coord(ys[u], v1, r1);
        const int k = voxel_coord(zs[u], v2, r2);
        if ((unsigned)i < NGRID && (unsigned)j < NGRID && (unsigned)k < NGRID) {
            const unsigned lin =
                (((unsigned)b * NGRID + i) * NGRID + j) * NGRID + k;
            atomicOr(&g_mask[t][lin >> 5], 1u << (lin & 31u));
        }
    }
}

// ---------------------------------------------------------------------------
// Kernel 3: expand bitmasks into the output tensor (READ-ONLY on the mask).
// 8 float4 per thread: each warp owns 256 CONSECUTIVE voxels; element u of
// each lane hits base + u*32 + lane -> every STG.128 lane-contiguous (full
// 512 B per warp instruction), 8-deep store ILP. Mask: two independent
// broadcast LDG.128 per tensor per warp (issued back-to-back for MLP).
// 512-thread blocks halve block count vs R14.
// ---------------------------------------------------------------------------
__global__ void __launch_bounds__(512, 2)
expand_kernel(float4* __restrict__ out, const float* __restrict__ emb) {
    const unsigned gwarp = (blockIdx.x * blockDim.x + threadIdx.x) >> 5;
    const unsigned lane  = threadIdx.x & 31u;
    const unsigned base  = gwarp * 256u;     // first voxel of this warp
    const unsigned w0    = base >> 5;        // first of 8 mask words (16B align)

    // 4 independent broadcast LDG.128s, all in flight together
    const uint4 va0 = *(const uint4*)&g_mask[0][w0];
    const uint4 va1 = *(const uint4*)&g_mask[0][w0 + 4u];
    const uint4 vb0 = *(const uint4*)&g_mask[1][w0];
    const uint4 vb1 = *(const uint4*)&g_mask[1][w0 + 4u];

    const unsigned wa[8] = {va0.x, va0.y, va0.z, va0.w,
                            va1.x, va1.y, va1.z, va1.w};
    const unsigned wb[8] = {vb0.x, vb0.y, vb0.z, vb0.w,
                            vb1.x, vb1.y, vb1.z, vb1.w};

    const float e00 = __ldg(&emb[0]);
    const float e01 = __ldg(&emb[1]);
    const float e10 = __ldg(&emb[2]);
    const float e11 = __ldg(&emb[3]);

#pragma unroll
    for (int u = 0; u < 8; u++) {
        const bool a = (wa[u] >> lane) & 1u;
        const bool c = (wb[u] >> lane) & 1u;
        out[base + (unsigned)u * 32u + lane] =
            make_float4(a ? e00 : 0.0f, a ? e01 : 0.0f,
                        c ? e10 : 0.0f, c ? e11 : 0.0f);
    }
}

// ---------------------------------------------------------------------------
// Launch (3 graph nodes: zero -> scatter -> expand)
// Inputs (metadata order): points_a [4,200000,3] f32, points_b [4,200000,3] f32,
//                          neck_voxel_sizes [4,3] f32, embedding_weight [2,2] f32
// Output: [4,128,128,128,4] f32  (33,554,432 floats)
// ---------------------------------------------------------------------------
extern "C" void kernel_launch(void* const* d_in, const int* in_sizes, int n_in,
                              void* d_out, int out_size) {
    const float* pts_a = (const float*)d_in[0];
    const float* pts_b = (const float*)d_in[1];
    const float* vs    = (const float*)d_in[2];
    const float* emb   = (const float*)d_in[3];

    // 1) zero mask (2 MB) — absorbs the first-node fixed tax
    zero_kernel<<<131072 / 256, 256>>>();

    // 2) scatter: (ceil(NPTS/4/256), BATCH, 2) blocks, 4 points per thread
    dim3 sgrid((NPTS / PTS_PER_THREAD + 255) / 256, BATCH, 2);
    scatter_kernel<<<sgrid, 256>>>(pts_a, pts_b, vs);

    // 3) expand: NVOX/8 threads in 512-thread blocks, 8 float4 stores each
    expand_kernel<<<(NVOX / 8) / 512, 512>>>((float4*)d_out, emb);
}

// round 16
// speedup vs baseline: 1.0082x; 1.0082x over previous
#include <cuda_runtime.h>
#include <cstdint>

// Problem constants
#define BATCH 4
#define NPTS  200000
#define NGRID 128            // NX = NY = NZ = 128
#define NVOX  (BATCH * NGRID * NGRID * NGRID)   // 8,388,608 voxels
#define NWORDS (NVOX / 32)                      // 262,144 uint32 per tensor
#define PTS_PER_THREAD 4

// Scratch: 2 tensors x 1 MB bitmask (static device array, no alloc).
// ENTRY INVARIANT: mask all-zero at kernel_launch entry.
//   - first call: module-load zero-initialization
//   - later calls/replays: warp-private trailing clear inside expand_kernel
__device__ unsigned int g_mask[2][NWORDS];

// ---------------------------------------------------------------------------
// Kernel 1: scatter points into occupancy bitmasks (RED.OR, L2-resident).
// At its measured floor (~7 us warmed = spread-atomic wavefront throughput;
// R12/R13 proved issue rate and load MLP are not binding). 4 points/thread
// via 3 x LDG.128. Reciprocals once per block via smem — bit-identical to
// per-thread __fdiv_rn (rel_err == 0.0 verified since R3).
//
// Numeric model: XLA arcp form  q = (p - 0.5*v) * (1/v), 1/v correctly
// rounded. rintf = round-half-even = jnp.round.
// ---------------------------------------------------------------------------
__device__ __forceinline__ int voxel_coord(float p, float v, float rinv) {
    float half    = __fmul_rn(v, 0.5f);        // exact
    float shifted = __fsub_rn(p, half);        // IEEE sub
    float q       = __fmul_rn(shifted, rinv);  // multiply by CR reciprocal
    return (int)rintf(q) + 64;
}

__global__ void scatter_kernel(const float* __restrict__ pts_a,
                               const float* __restrict__ pts_b,
                               const float* __restrict__ vs) {
    const int b = blockIdx.y;                  // batch
    const int t = blockIdx.z;                  // tensor (0=a, 1=b)

    __shared__ float s_v[3], s_r[3];
    if (threadIdx.x < 3u) {
        const float v = vs[b * 3 + threadIdx.x];
        s_v[threadIdx.x] = v;
        s_r[threadIdx.x] = __fdiv_rn(1.0f, v); // CR reciprocal, once per block
    }
    __syncthreads();

    const unsigned tid = blockIdx.x * blockDim.x + threadIdx.x;
    const unsigned p0  = tid * PTS_PER_THREAD;           // first point
    if (p0 >= NPTS) return;                              // NPTS % 4 == 0

    const float* __restrict__ pts =
        ((t == 0) ? pts_a : pts_b) + (size_t)b * (NPTS * 3);

    // 4 points = 12 floats = 3 x float4 (16 B aligned)
    const float4* __restrict__ q4 = (const float4*)(pts + (size_t)p0 * 3);
    const float4 A = q4[0];
    const float4 B = q4[1];
    const float4 C = q4[2];

    const float xs[4] = {A.x, A.w, B.z, C.y};
    const float ys[4] = {A.y, B.x, B.w, C.z};
    const float zs[4] = {A.z, B.y, C.x, C.w};

    const float v0 = s_v[0], v1 = s_v[1], v2 = s_v[2];
    const float r0 = s_r[0], r1 = s_r[1], r2 = s_r[2];

#pragma unroll
    for (int u = 0; u < 4; u++) {
        const int i = voxel_coord(xs[u], v0, r0);
        const int j = voxel_coord(ys[u], v1, r1);
        const int k = voxel_coord(zs[u], v2, r2);
        if ((unsigned)i < NGRID && (unsigned)j < NGRID && (unsigned)k < NGRID) {
            const unsigned lin =
                (((unsigned)b * NGRID + i) * NGRID + j) * NGRID + k;
            atomicOr(&g_mask[t][lin >> 5], 1u << (lin & 31u));
        }
    }
}

// ---------------------------------------------------------------------------
// Kernel 2: expand bitmasks into the output tensor, then WARP-PRIVATE
// trailing clear of the mask (restores the entry invariant for next call).
//
// Layout: each warp owns 256 CONSECUTIVE voxels = mask words [w0, w0+8) per
// tensor, read by NO other warp. Element u of each lane hits base+u*32+lane
// -> every STG.128 lane-contiguous (full 512 B per warp instruction), 8-deep
// store ILP.
//
// Clear placement is AFTER the output stores (every failed variant R4/R6/R10
// cleared BEFORE them): in-order STG issue means all 8 LDG-sourced stores
// have consumed the mask data before the 4 zero-uint4 stores (lanes 0-3)
// issue, and the words are warp-exclusive, so no barrier of any kind is
// needed beyond __syncwarp.
// ---------------------------------------------------------------------------
__global__ void __launch_bounds__(512, 2)
expand_kernel(float4* __restrict__ out, const float* __restrict__ emb) {
    const unsigned gwarp = (blockIdx.x * blockDim.x + threadIdx.x) >> 5;
    const unsigned lane  = threadIdx.x & 31u;
    const unsigned base  = gwarp * 256u;     // first voxel of this warp
    const unsigned w0    = base >> 5;        // first of 8 mask words (16B align)

    // 4 independent broadcast LDG.128s, all in flight together
    const uint4 va0 = *(const uint4*)&g_mask[0][w0];
    const uint4 va1 = *(const uint4*)&g_mask[0][w0 + 4u];
    const uint4 vb0 = *(const uint4*)&g_mask[1][w0];
    const uint4 vb1 = *(const uint4*)&g_mask[1][w0 + 4u];

    const unsigned wa[8] = {va0.x, va0.y, va0.z, va0.w,
                            va1.x, va1.y, va1.z, va1.w};
    const unsigned wb[8] = {vb0.x, vb0.y, vb0.z, vb0.w,
                            vb1.x, vb1.y, vb1.z, vb1.w};

    const float e00 = __ldg(&emb[0]);
    const float e01 = __ldg(&emb[1]);
    const float e10 = __ldg(&emb[2]);
    const float e11 = __ldg(&emb[3]);

#pragma unroll
    for (int u = 0; u < 8; u++) {
        const bool a = (wa[u] >> lane) & 1u;
        const bool c = (wb[u] >> lane) & 1u;
        out[base + (unsigned)u * 32u + lane] =
            make_float4(a ? e00 : 0.0f, a ? e01 : 0.0f,
                        c ? e10 : 0.0f, c ? e11 : 0.0f);
    }

    // Warp-private trailing clear: 4 zero-uint4 stores cover this warp's
    // 8 words in each tensor. Issued strictly after the output stores above.
    __syncwarp();
    if (lane < 2u)
        *(uint4*)&g_mask[0][w0 + lane * 4u] = make_uint4(0u, 0u, 0u, 0u);
    else if (lane < 4u)
        *(uint4*)&g_mask[1][w0 + (lane - 2u) * 4u] = make_uint4(0u, 0u, 0u, 0u);
}

// ---------------------------------------------------------------------------
// Launch (2 graph nodes: scatter -> expand) — one fewer node than R14/R15
// (~2.8 us per-node overhead per B300 T_ovh).
// Inputs (metadata order): points_a [4,200000,3] f32, points_b [4,200000,3] f32,
//                          neck_voxel_sizes [4,3] f32, embedding_weight [2,2] f32
// Output: [4,128,128,128,4] f32  (33,554,432 floats)
// ---------------------------------------------------------------------------
extern "C" void kernel_launch(void* const* d_in, const int* in_sizes, int n_in,
                              void* d_out, int out_size) {
    const float* pts_a = (const float*)d_in[0];
    const float* pts_b = (const float*)d_in[1];
    const float* vs    = (const float*)d_in[2];
    const float* emb   = (const float*)d_in[3];

    // 1) scatter: (ceil(NPTS/4/256), BATCH, 2) blocks, 4 points per thread
    dim3 sgrid((NPTS / PTS_PER_THREAD + 255) / 256, BATCH, 2);
    scatter_kernel<<<sgrid, 256>>>(pts_a, pts_b, vs);

    // 2) expand + warp-private trailing clear:
    //    NVOX/8 threads in 512-thread blocks, 8 float4 stores each
    expand_kernel<<<(NVOX / 8) / 512, 512>>>((float4*)d_out, emb);
}